// round 16
// baseline (speedup 1.0000x reference)
#include <cuda_runtime.h>
#include <cuda_bf16.h>
#include <cstdint>
#include <cmath>

// ---------------- problem constants ----------------
constexpr int B    = 2;
constexpr int S    = 2048;
constexpr int HV   = 16;
constexpr int CCH  = 3072;
constexpr int MTOK = B * S;   // 4096
constexpr int KT   = 3072;    // split-K (3 x 1024)
constexpr int NP   = 4352;    // merged projection cols (3072 qkv + 1280 ab-pad)

// ---------------- scratch (device globals) ----------------
__device__ float g_proj[(size_t)MTOK * NP];    // qkv | a | b | gate
__device__ float g_conv[(size_t)MTOK * CCH];   // silu(conv), q/k normalized
__device__ float g_eg  [MTOK * HV];            // exp(g)
__device__ float g_beta[MTOK * HV];
__device__ float g_oatt[(size_t)MTOK * 1024];
__device__ __nv_bfloat16 g_hid2[(size_t)MTOK * KT];
__device__ __nv_bfloat16 g_w2  [(size_t)NP * KT];     // merged qkv+ab weights
__device__ __nv_bfloat16 g_wo2 [(size_t)1024 * KT];
__device__ __nv_bfloat16 g_on2 [(size_t)MTOK * KT];

// ---------------- helpers ----------------
__device__ __forceinline__ uint32_t smem_u32(const void* p) {
    uint32_t a;
    asm("{ .reg .u64 t; cvta.to.shared.u64 t, %1; cvt.u32.u64 %0, t; }" : "=r"(a) : "l"(p));
    return a;
}
#define CP_ASYNC16(s, g) asm volatile("cp.async.cg.shared.global [%0], [%1], 16;" :: "r"(s), "l"(g))
#define CP_ASYNC4(s, g)  asm volatile("cp.async.ca.shared.global [%0], [%1], 4;"  :: "r"(s), "l"(g))
#define CP_COMMIT()      asm volatile("cp.async.commit_group;")
#define CP_WAIT1()       asm volatile("cp.async.wait_group 1;" ::: "memory")
#define CP_WAIT2()       asm volatile("cp.async.wait_group 2;")

__device__ __forceinline__ void ldsm4(uint32_t (&r)[4], uint32_t addr) {
    asm volatile("ldmatrix.sync.aligned.m8n8.x4.shared.b16 {%0,%1,%2,%3}, [%4];"
                 : "=r"(r[0]), "=r"(r[1]), "=r"(r[2]), "=r"(r[3]) : "r"(addr));
}
__device__ __forceinline__ void mma16816(float (&d)[4], const uint32_t a0, const uint32_t a1,
                                         const uint32_t a2, const uint32_t a3,
                                         const uint32_t b0, const uint32_t b1) {
    asm volatile("mma.sync.aligned.m16n8k16.row.col.f32.bf16.bf16.f32 "
                 "{%0,%1,%2,%3}, {%4,%5,%6,%7}, {%8,%9}, {%0,%1,%2,%3};"
                 : "+f"(d[0]), "+f"(d[1]), "+f"(d[2]), "+f"(d[3])
                 : "r"(a0), "r"(a1), "r"(a2), "r"(a3), "r"(b0), "r"(b1));
}

// ---------------- ALL fp32 -> bf16 hi/lo splits in one launch ----------------
constexpr int SP_ROWS = 9472;
__global__ void split_all(const float* __restrict__ hidden, const float* __restrict__ wqkv,
                          const float* __restrict__ wab, const float* __restrict__ wo)
{
    int idx = blockIdx.x * blockDim.x + threadIdx.x;
    if (idx >= SP_ROWS * 1024) return;
    int row = idx >> 10, c = idx & 1023;
    float x;
    __nv_bfloat16* out;
    size_t o;
    int wmode = 1;
    if (row < 4096) {
        x = hidden[idx]; out = g_hid2; o = (size_t)row * KT + c; wmode = 0;
    } else if (row < 7168) {
        int r = row - 4096; x = wqkv[(size_t)r * 1024 + c]; out = g_w2; o = (size_t)r * KT + c;
    } else if (row < 8448) {
        int r = row - 7168; x = (r < 1056) ? wab[(size_t)r * 1024 + c] : 0.f;
        out = g_w2; o = (size_t)(r + 3072) * KT + c;
    } else {
        int r = row - 8448; x = wo[(size_t)r * 1024 + c]; out = g_wo2; o = (size_t)r * KT + c;
    }
    __nv_bfloat16 hi = __float2bfloat16(x);
    __nv_bfloat16 lo = __float2bfloat16(x - __bfloat162float(hi));
    out[o]        = hi;
    out[o + 1024] = wmode ? lo : hi;
    out[o + 2048] = wmode ? hi : lo;
}

// ---------------- HMMA bf16 NT GEMM (unchanged from R8) ----------------------
constexpr int BK   = 64;
constexpr int LDW  = 72;
constexpr int SGA  = 128 * LDW * 2;
constexpr int SGB  = 256 * LDW * 2;
constexpr int STG  = 4;
constexpr int GEMM_SMEM = STG * (SGA + SGB);  // 221184

__global__ __launch_bounds__(256, 1) void gemm_hmma(
    const __nv_bfloat16* __restrict__ A2,
    const __nv_bfloat16* __restrict__ W2,
    float* __restrict__ C, int N)
{
    extern __shared__ __align__(16) __nv_bfloat16 smem_dyn[];

    const int tid  = threadIdx.x;
    const int wid  = tid >> 5;
    const int lane = tid & 31;
    const int wm   = wid & 1;
    const int wn   = wid >> 1;

    const int m0 = blockIdx.y * 128;
    const int n0 = blockIdx.x * 256;
    const __nv_bfloat16* Abase = A2 + (size_t)m0 * KT;
    const __nv_bfloat16* Wbase = W2 + (size_t)n0 * KT;

    const uint32_t smA = smem_u32(smem_dyn);
    const uint32_t smB = smA + STG * SGA;

    const int lr = tid >> 3;
    const int lc = tid & 7;

    auto loadStage = [&](int it) {
        const int buf = it & 3;
        const int kc0 = it * BK;
        const uint32_t dA = smA + buf * SGA;
        const uint32_t dB = smB + buf * SGB;
#pragma unroll
        for (int i = 0; i < 4; i++) {
            const int r = lr + i * 32;
            CP_ASYNC16(dA + (r * LDW + lc * 8) * 2, Abase + (size_t)r * KT + kc0 + lc * 8);
        }
#pragma unroll
        for (int i = 0; i < 8; i++) {
            const int r = lr + i * 32;
            CP_ASYNC16(dB + (r * LDW + lc * 8) * 2, Wbase + (size_t)r * KT + kc0 + lc * 8);
        }
    };

    float acc[4][8][4];
#pragma unroll
    for (int i = 0; i < 4; i++)
#pragma unroll
        for (int j = 0; j < 8; j++)
#pragma unroll
            for (int k = 0; k < 4; k++) acc[i][j][k] = 0.f;

    const int aRow = wm * 64 + (lane & 15);
    const int aColSel = (lane >> 4) * 8;
    const int bRow = wn * 64 + (lane >> 4) * 8 + (lane & 7);
    const int bColSel = ((lane >> 3) & 1) * 8;

    constexpr int NIT = KT / BK;

    loadStage(0); CP_COMMIT();
    loadStage(1); CP_COMMIT();
    loadStage(2); CP_COMMIT();

    for (int it = 0; it < NIT; it++) {
        CP_WAIT2();
        __syncthreads();

        if (it + 3 < NIT) loadStage(it + 3);
        CP_COMMIT();

        const int buf = it & 3;
        const uint32_t aB = smA + buf * SGA;
        const uint32_t bB = smB + buf * SGB;
        const uint32_t aAddr = aB + (aRow * LDW + aColSel) * 2;
        const uint32_t bAddr = bB + (bRow * LDW + bColSel) * 2;

        uint32_t ra[2][4][4], rb[2][4][4];
#pragma unroll
        for (int mt = 0; mt < 4; mt++) ldsm4(ra[0][mt], aAddr + mt * (16 * LDW * 2));
#pragma unroll
        for (int pr = 0; pr < 4; pr++) ldsm4(rb[0][pr], bAddr + pr * (16 * LDW * 2));

#pragma unroll
        for (int kk = 0; kk < BK; kk += 16) {
            const int cur = (kk >> 4) & 1;
            const int nxt = cur ^ 1;
            if (kk + 16 < BK) {
#pragma unroll
                for (int mt = 0; mt < 4; mt++)
                    ldsm4(ra[nxt][mt], aAddr + (kk + 16) * 2 + mt * (16 * LDW * 2));
#pragma unroll
                for (int pr = 0; pr < 4; pr++)
                    ldsm4(rb[nxt][pr], bAddr + (kk + 16) * 2 + pr * (16 * LDW * 2));
            }
#pragma unroll
            for (int mt = 0; mt < 4; mt++)
#pragma unroll
                for (int nt = 0; nt < 8; nt++)
                    mma16816(acc[mt][nt],
                             ra[cur][mt][0], ra[cur][mt][1], ra[cur][mt][2], ra[cur][mt][3],
                             rb[cur][nt >> 1][(nt & 1) * 2], rb[cur][nt >> 1][(nt & 1) * 2 + 1]);
        }
    }

#pragma unroll
    for (int mt = 0; mt < 4; mt++) {
#pragma unroll
        for (int nt = 0; nt < 8; nt++) {
            const int row = m0 + wm * 64 + mt * 16 + (lane >> 2);
            const int col = n0 + wn * 64 + nt * 8 + (lane & 3) * 2;
            *(float2*)(C + (size_t)row * N + col) =
                make_float2(acc[mt][nt][0], acc[mt][nt][1]);
            *(float2*)(C + (size_t)(row + 8) * N + col) =
                make_float2(acc[mt][nt][2], acc[mt][nt][3]);
        }
    }
}

// ---------------- conv(4)+SiLU+L2norm AND gate-param transform ---------------
constexpr int CONV_BLOCKS = MTOK * 48 / 8;   // 24576
__global__ __launch_bounds__(256) void conv_ab(const float* __restrict__ wconv,
                                               const float* __restrict__ A_log,
                                               const float* __restrict__ dt_bias)
{
    if (blockIdx.x >= CONV_BLOCKS) {
        const int idx = (blockIdx.x - CONV_BLOCKS) * 256 + threadIdx.x;
        if (idx >= MTOK * HV) return;
        const int t = idx >> 4, h = idx & 15;
        const float a  = g_proj[(size_t)t * NP + 3072 + h];
        const float bb = g_proj[(size_t)t * NP + 3072 + 16 + h];
        const float x  = a + dt_bias[h];
        const float sp = (x > 20.f) ? x : log1pf(expf(x));
        g_eg[idx]   = expf(-expf(A_log[h]) * sp);
        g_beta[idx] = 1.f / (1.f + expf(-bb));
        return;
    }
    const int gi   = blockIdx.x * 8 + (threadIdx.x >> 5);
    const int t    = gi / 48;
    const int grp  = gi % 48;
    const int lane = threadIdx.x & 31;
    const int batch = t >> 11;
    const int s     = t & 2047;

    float y[2];
#pragma unroll
    for (int hh = 0; hh < 2; hh++) {
        const int c = grp * 64 + lane + hh * 32;
        float acc = 0.f;
#pragma unroll
        for (int i = 0; i < 4; i++) {
            const int ss = s - 3 + i;
            if (ss >= 0)
                acc = fmaf(g_proj[(size_t)(batch * S + ss) * NP + c], wconv[c * 4 + i], acc);
        }
        y[hh] = acc / (1.f + expf(-acc));
    }
    if (grp < 32) {
        float ssum = y[0] * y[0] + y[1] * y[1];
#pragma unroll
        for (int o = 16; o; o >>= 1) ssum += __shfl_xor_sync(0xffffffffu, ssum, o);
        float inv = rsqrtf(ssum + 1e-6f);
        if (grp < 16) inv *= 0.125f;
        y[0] *= inv; y[1] *= inv;
    }
    g_conv[(size_t)t * CCH + grp * 64 + lane]      = y[0];
    g_conv[(size_t)t * CCH + grp * 64 + lane + 32] = y[1];
}

// ---------------- sequential gated delta scan: v-split 8x, 4 thr/col ---------
// grid 256 = (b,h) x 8 v-slices (8 cols). 32 threads: thread (v = tid>>2,
// r = tid&3) owns k-rows [r*16, r*16+16) of column vc0+v. Only TWO shfls on
// the serial chain (vs 3 at 8 thr/col). 256 single-warp CTAs spread over SMs.
__global__ __launch_bounds__(32, 1) void scan_kernel()
{
    constexpr int CH = 32;
    constexpr int VC = 8;
    const int bh  = blockIdx.x >> 3;
    const int vc0 = (blockIdx.x & 7) * VC;
    const int b   = bh >> 4, h = bh & 15;
    const int tid = threadIdx.x;
    const int v   = tid >> 2;        // 0..7 (local v column)
    const int r   = tid & 3;         // 16 k-elements each

    __shared__ __align__(16) float sq[2][CH][64], sk[2][CH][64], sv[2][CH][VC];
    __shared__ float seg[2][CH], sbeta[2][CH];

    const float* convBase = g_conv + (size_t)(b * S) * CCH;

    auto issueChunk = [&](int c64) {
        const int buf = c64 & 1;
        const int c0 = c64 * CH;
#pragma unroll
        for (int i = 0; i < 16; i++) {
            const int chunk = tid + i * 32;            // 0..511
            const int st = chunk >> 4, d4 = chunk & 15;
            const size_t row = (size_t)(c0 + st) * CCH + h * 64 + d4 * 4;
            CP_ASYNC16(smem_u32(&sq[buf][st][d4 * 4]), convBase + row);
            CP_ASYNC16(smem_u32(&sk[buf][st][d4 * 4]), convBase + row + 1024);
        }
#pragma unroll
        for (int i = 0; i < 2; i++) {                  // sv: 64 float4
            const int chunk = tid + i * 32;
            const int st = chunk >> 1, d4 = chunk & 1;
            CP_ASYNC16(smem_u32(&sv[buf][st][d4 * 4]),
                       convBase + (size_t)(c0 + st) * CCH + 2048 + h * 64 + vc0 + d4 * 4);
        }
        {
            const int token = b * S + c0 + tid;
            CP_ASYNC4(smem_u32(&seg[buf][tid]),   g_eg   + token * HV + h);
            CP_ASYNC4(smem_u32(&sbeta[buf][tid]), g_beta + token * HV + h);
        }
    };

    float hst[16];
#pragma unroll
    for (int j = 0; j < 16; j++) hst[j] = 0.f;

    issueChunk(0); CP_COMMIT();

    for (int c64 = 0; c64 < S / CH; c64++) {
        if (c64 + 1 < S / CH) issueChunk(c64 + 1);
        CP_COMMIT();
        CP_WAIT1();
        __syncwarp();
        const int buf = c64 & 1;
        const int c0 = c64 * CH;

        // ---- software pipeline: preload step 0 k + coefs
        float4 ck0 = *(const float4*)&sk[buf][0][r * 16];
        float4 ck1 = *(const float4*)&sk[buf][0][r * 16 + 4];
        float4 ck2 = *(const float4*)&sk[buf][0][r * 16 + 8];
        float4 ck3 = *(const float4*)&sk[buf][0][r * 16 + 12];
        float ce    = seg[buf][0];
        float cbt   = sbeta[buf][0];
        float cnbte = -cbt * ce;
        float cbtv  = cbt * sv[buf][0][v];

#pragma unroll 4
        for (int st = 0; st < CH; st++) {
            // prefetch step st+1 (off the h-chain)
            const int sn = (st + 1 < CH) ? st + 1 : st;
            const float4 nk0 = *(const float4*)&sk[buf][sn][r * 16];
            const float4 nk1 = *(const float4*)&sk[buf][sn][r * 16 + 4];
            const float4 nk2 = *(const float4*)&sk[buf][sn][r * 16 + 8];
            const float4 nk3 = *(const float4*)&sk[buf][sn][r * 16 + 12];
            const float ne    = seg[buf][sn];
            const float nbt   = sbeta[buf][sn];
            const float nnbte = -nbt * ne;
            const float nbtv  = nbt * sv[buf][sn][v];

            // q for current step (off critical chain)
            const float4 q0 = *(const float4*)&sq[buf][st][r * 16];
            const float4 q1 = *(const float4*)&sq[buf][st][r * 16 + 4];
            const float4 q2 = *(const float4*)&sq[buf][st][r * 16 + 8];
            const float4 q3 = *(const float4*)&sq[buf][st][r * 16 + 12];

            // ---- kv dot (16 elems, 4 parallel chains)
            float cA = fmaf(ck0.x, hst[0], ck0.y * hst[1]);
            cA = fmaf(ck0.z, hst[2], cA);  cA = fmaf(ck0.w, hst[3], cA);
            float cB = fmaf(ck1.x, hst[4], ck1.y * hst[5]);
            cB = fmaf(ck1.z, hst[6], cB);  cB = fmaf(ck1.w, hst[7], cB);
            float cC = fmaf(ck2.x, hst[8], ck2.y * hst[9]);
            cC = fmaf(ck2.z, hst[10], cC); cC = fmaf(ck2.w, hst[11], cC);
            float cD = fmaf(ck3.x, hst[12], ck3.y * hst[13]);
            cD = fmaf(ck3.z, hst[14], cD); cD = fmaf(ck3.w, hst[15], cD);
            float s1 = (cA + cB) + (cC + cD);
            s1 += __shfl_xor_sync(0xffffffffu, s1, 1);
            s1 += __shfl_xor_sync(0xffffffffu, s1, 2);
            const float delta = fmaf(cnbte, s1, cbtv);

            const float kk[16] = {ck0.x,ck0.y,ck0.z,ck0.w, ck1.x,ck1.y,ck1.z,ck1.w,
                                  ck2.x,ck2.y,ck2.z,ck2.w, ck3.x,ck3.y,ck3.z,ck3.w};
            const float qq[16] = {q0.x,q0.y,q0.z,q0.w, q1.x,q1.y,q1.z,q1.w,
                                  q2.x,q2.y,q2.z,q2.w, q3.x,q3.y,q3.z,q3.w};

            float oA = 0.f, oB = 0.f, oC = 0.f, oD = 0.f;
#pragma unroll
            for (int j = 0; j < 4; j++) {
                hst[j] = fmaf(hst[j], ce, kk[j] * delta);
                oA = fmaf(qq[j], hst[j], oA);
            }
#pragma unroll
            for (int j = 4; j < 8; j++) {
                hst[j] = fmaf(hst[j], ce, kk[j] * delta);
                oB = fmaf(qq[j], hst[j], oB);
            }
#pragma unroll
            for (int j = 8; j < 12; j++) {
                hst[j] = fmaf(hst[j], ce, kk[j] * delta);
                oC = fmaf(qq[j], hst[j], oC);
            }
#pragma unroll
            for (int j = 12; j < 16; j++) {
                hst[j] = fmaf(hst[j], ce, kk[j] * delta);
                oD = fmaf(qq[j], hst[j], oD);
            }
            float oo = (oA + oB) + (oC + oD);
            oo += __shfl_xor_sync(0xffffffffu, oo, 1);
            oo += __shfl_xor_sync(0xffffffffu, oo, 2);
            if (r == 0)
                g_oatt[((size_t)(b * S + c0 + st) * HV + h) * 64 + vc0 + v] = oo;

            // rotate pipeline registers
            ck0 = nk0; ck1 = nk1; ck2 = nk2; ck3 = nk3;
            ce = ne; cnbte = nnbte; cbtv = nbtv;
        }
        __syncwarp();      // all reads of buf done before next issue overwrites it
    }
}

// ---------------- gate*silu + RMSNorm, writes bf16 [hi|hi|lo] ----------------
__global__ __launch_bounds__(128) void gate_norm(const float* __restrict__ rms_w)
{
    const int gidx = blockIdx.x * 4 + (threadIdx.x >> 5);
    const int lane = threadIdx.x & 31;
    const int t = gidx >> 4, h = gidx & 15;
    const size_t base = (size_t)gidx * 64;

    float x[2];
#pragma unroll
    for (int hh = 0; hh < 2; hh++) {
        const int d = lane + hh * 32;
        const float o  = g_oatt[base + d];
        const float gt = g_proj[(size_t)t * NP + 3072 + 32 + h * 64 + d];
        x[hh] = o * (gt / (1.f + expf(-gt)));
    }
    float ms = x[0] * x[0] + x[1] * x[1];
#pragma unroll
    for (int o = 16; o; o >>= 1) ms += __shfl_xor_sync(0xffffffffu, ms, o);
    const float inv = rsqrtf(ms * (1.f / 64.f) + 1e-5f);
#pragma unroll
    for (int hh = 0; hh < 2; hh++) {
        const int d = lane + hh * 32;
        const float y = x[hh] * inv * rms_w[d];
        __nv_bfloat16 hi = __float2bfloat16(y);
        __nv_bfloat16 lo = __float2bfloat16(y - __bfloat162float(hi));
        const size_t o = (size_t)t * KT + h * 64 + d;
        g_on2[o]        = hi;
        g_on2[o + 1024] = hi;
        g_on2[o + 2048] = lo;
    }
}

// ---------------- launch ----------------------------------------------------
extern "C" void kernel_launch(void* const* d_in, const int* in_sizes, int n_in,
                              void* d_out, int out_size)
{
    const float* hidden  = (const float*)d_in[0];
    const float* w_qkv   = (const float*)d_in[1];
    const float* w_ab    = (const float*)d_in[2];
    const float* w_conv  = (const float*)d_in[3];
    const float* A_log   = (const float*)d_in[4];
    const float* dt_bias = (const float*)d_in[5];
    const float* rms_w   = (const float*)d_in[6];
    const float* w_o     = (const float*)d_in[7];
    float* out = (float*)d_out;

    float* p_proj;
    __nv_bfloat16 *p_hid2, *p_w2, *p_wo2, *p_on2;
    cudaGetSymbolAddress((void**)&p_proj, g_proj);
    cudaGetSymbolAddress((void**)&p_hid2, g_hid2);
    cudaGetSymbolAddress((void**)&p_w2,   g_w2);
    cudaGetSymbolAddress((void**)&p_wo2,  g_wo2);
    cudaGetSymbolAddress((void**)&p_on2,  g_on2);

    cudaFuncSetAttribute(gemm_hmma, cudaFuncAttributeMaxDynamicSharedMemorySize, GEMM_SMEM);

    // 1) all bf16 hi/lo splits
    split_all<<<SP_ROWS * 1024 / 256, 256>>>(hidden, w_qkv, w_ab, w_o);

    // 2) merged input projection (tensor cores)
    gemm_hmma<<<dim3(NP / 256, MTOK / 128), 256, GEMM_SMEM>>>(p_hid2, p_w2, p_proj, NP);

    // 3) conv + gate params
    conv_ab<<<CONV_BLOCKS + MTOK * HV / 256, 256>>>(w_conv, A_log, dt_bias);

    // 4) recurrent scan (v-split 8x, 4 thr/col, 2-shfl chain) -- profiled
    scan_kernel<<<B * HV * 8, 32>>>();

    // 5) gating + norm ; 6) output projection
    gate_norm<<<MTOK * HV / 4, 128>>>(rms_w);
    gemm_hmma<<<dim3(1024 / 256, MTOK / 128), 256, GEMM_SMEM>>>(p_on2, p_wo2, out, 1024);
}

// round 17
// speedup vs baseline: 1.0756x; 1.0756x over previous
#include <cuda_runtime.h>
#include <cuda_bf16.h>
#include <cstdint>
#include <cmath>

// ---------------- problem constants ----------------
constexpr int B    = 2;
constexpr int S    = 2048;
constexpr int HV   = 16;
constexpr int CCH  = 3072;
constexpr int MTOK = B * S;   // 4096
constexpr int KT   = 3072;    // split-K (3 x 1024)
constexpr int NP   = 4352;    // merged projection cols (3072 qkv + 1280 ab-pad)

// ---------------- scratch (device globals) ----------------
__device__ float g_proj[(size_t)MTOK * NP];    // qkv | a | b | gate
__device__ float g_conv[(size_t)MTOK * CCH];   // silu(conv), q/k normalized
__device__ float g_eg  [MTOK * HV];            // exp(g)
__device__ float g_beta[MTOK * HV];
__device__ float g_oatt[(size_t)MTOK * 1024];
__device__ __nv_bfloat16 g_hid2[(size_t)MTOK * KT];
__device__ __nv_bfloat16 g_w2  [(size_t)NP * KT];     // merged qkv+ab weights
__device__ __nv_bfloat16 g_wo2 [(size_t)1024 * KT];
__device__ __nv_bfloat16 g_on2 [(size_t)MTOK * KT];

// ---------------- helpers ----------------
__device__ __forceinline__ uint32_t smem_u32(const void* p) {
    uint32_t a;
    asm("{ .reg .u64 t; cvta.to.shared.u64 t, %1; cvt.u32.u64 %0, t; }" : "=r"(a) : "l"(p));
    return a;
}
#define CP_ASYNC16(s, g) asm volatile("cp.async.cg.shared.global [%0], [%1], 16;" :: "r"(s), "l"(g))
#define CP_ASYNC4(s, g)  asm volatile("cp.async.ca.shared.global [%0], [%1], 4;"  :: "r"(s), "l"(g))
#define CP_COMMIT()      asm volatile("cp.async.commit_group;")
#define CP_WAIT1()       asm volatile("cp.async.wait_group 1;" ::: "memory")

__device__ __forceinline__ void ldsm4(uint32_t (&r)[4], uint32_t addr) {
    asm volatile("ldmatrix.sync.aligned.m8n8.x4.shared.b16 {%0,%1,%2,%3}, [%4];"
                 : "=r"(r[0]), "=r"(r[1]), "=r"(r[2]), "=r"(r[3]) : "r"(addr));
}
__device__ __forceinline__ void mma16816(float (&d)[4], const uint32_t a0, const uint32_t a1,
                                         const uint32_t a2, const uint32_t a3,
                                         const uint32_t b0, const uint32_t b1) {
    asm volatile("mma.sync.aligned.m16n8k16.row.col.f32.bf16.bf16.f32 "
                 "{%0,%1,%2,%3}, {%4,%5,%6,%7}, {%8,%9}, {%0,%1,%2,%3};"
                 : "+f"(d[0]), "+f"(d[1]), "+f"(d[2]), "+f"(d[3])
                 : "r"(a0), "r"(a1), "r"(a2), "r"(a3), "r"(b0), "r"(b1));
}

// ---------------- fp32 -> bf16 hi/lo split (K-concatenated) ------------------
// wmode=0 (activations): [hi | hi | lo]; wmode=1 (weights): [hi | lo | hi]
__global__ void split3(const float* __restrict__ in, __nv_bfloat16* __restrict__ out,
                       int out_rows, int in_rows, int wmode)
{
    int idx = blockIdx.x * blockDim.x + threadIdx.x;
    if (idx >= out_rows * 1024) return;
    int row = idx >> 10, c = idx & 1023;
    float x = (row < in_rows) ? in[(size_t)row * 1024 + c] : 0.f;
    __nv_bfloat16 hi = __float2bfloat16(x);
    __nv_bfloat16 lo = __float2bfloat16(x - __bfloat162float(hi));
    size_t o = (size_t)row * KT + c;
    out[o]        = hi;
    out[o + 1024] = wmode ? lo : hi;
    out[o + 2048] = wmode ? hi : lo;
}

// w_ab (1056 real rows, pad to 1280) + w_o (1024 rows) in one launch
__global__ void split_rest(const float* __restrict__ wab, const float* __restrict__ wo)
{
    int idx = blockIdx.x * blockDim.x + threadIdx.x;
    if (idx >= 2304 * 1024) return;
    int row = idx >> 10, c = idx & 1023;
    float x;
    __nv_bfloat16* out;
    size_t o;
    if (row < 1280) {
        x = (row < 1056) ? wab[(size_t)row * 1024 + c] : 0.f;
        out = g_w2; o = (size_t)(row + 3072) * KT + c;
    } else {
        int r = row - 1280;
        x = wo[(size_t)r * 1024 + c];
        out = g_wo2; o = (size_t)r * KT + c;
    }
    __nv_bfloat16 hi = __float2bfloat16(x);
    __nv_bfloat16 lo = __float2bfloat16(x - __bfloat162float(hi));
    out[o]        = hi;
    out[o + 1024] = lo;
    out[o + 2048] = hi;
}

// ---------------- HMMA bf16 NT GEMM: 128x128 CTA, 2 CTAs/SM ------------------
// 4 warps (2m x 2n), warp tile 64x64 (8 ldsm / 32 mma), BK=64, 3-stage cp.async.
constexpr int BK   = 64;
constexpr int LDW  = 72;
constexpr int SGT  = 128 * LDW * 2;          // per-array stage bytes (18432)
constexpr int STG  = 3;
constexpr int GEMM_SMEM = STG * SGT * 2;     // 110592 -> 2 CTAs/SM

__global__ __launch_bounds__(128, 2) void gemm_hmma(
    const __nv_bfloat16* __restrict__ A2,
    const __nv_bfloat16* __restrict__ W2,
    float* __restrict__ C, int N)
{
    extern __shared__ __align__(16) __nv_bfloat16 smem_dyn[];

    const int tid  = threadIdx.x;
    const int wid  = tid >> 5;
    const int lane = tid & 31;
    const int wm   = wid & 1;        // 0..1 (64 rows)
    const int wn   = wid >> 1;       // 0..1 (64 cols)

    const int m0 = blockIdx.y * 128;
    const int n0 = blockIdx.x * 128;
    const __nv_bfloat16* Abase = A2 + (size_t)m0 * KT;
    const __nv_bfloat16* Wbase = W2 + (size_t)n0 * KT;

    const uint32_t smA = smem_u32(smem_dyn);
    const uint32_t smB = smA + STG * SGT;

    const int lr = tid >> 3;          // 0..15
    const int lc = tid & 7;           // 0..7 (16B chunks of 64-elem row)

    auto loadStage = [&](int it) {
        const int buf = it % STG;
        const int kc0 = it * BK;
        const uint32_t dA = smA + buf * SGT;
        const uint32_t dB = smB + buf * SGT;
#pragma unroll
        for (int i = 0; i < 8; i++) {          // A: 128 rows
            const int r = lr + i * 16;
            CP_ASYNC16(dA + (r * LDW + lc * 8) * 2, Abase + (size_t)r * KT + kc0 + lc * 8);
        }
#pragma unroll
        for (int i = 0; i < 8; i++) {          // B: 128 rows
            const int r = lr + i * 16;
            CP_ASYNC16(dB + (r * LDW + lc * 8) * 2, Wbase + (size_t)r * KT + kc0 + lc * 8);
        }
    };

    float acc[4][8][4];
#pragma unroll
    for (int i = 0; i < 4; i++)
#pragma unroll
        for (int j = 0; j < 8; j++)
#pragma unroll
            for (int k = 0; k < 4; k++) acc[i][j][k] = 0.f;

    const int aRow = wm * 64 + (lane & 15);
    const int aColSel = (lane >> 4) * 8;
    const int bRow = wn * 64 + (lane >> 4) * 8 + (lane & 7);
    const int bColSel = ((lane >> 3) & 1) * 8;

    constexpr int NIT = KT / BK;     // 48

    loadStage(0); CP_COMMIT();
    loadStage(1); CP_COMMIT();

    for (int it = 0; it < NIT; it++) {
        CP_WAIT1();
        __syncthreads();

        if (it + 2 < NIT) loadStage(it + 2);
        CP_COMMIT();

        const int buf = it % STG;
        const uint32_t aB = smA + buf * SGT;
        const uint32_t bB = smB + buf * SGT;
        const uint32_t aAddr = aB + (aRow * LDW + aColSel) * 2;
        const uint32_t bAddr = bB + (bRow * LDW + bColSel) * 2;

        uint32_t ra[2][4][4], rb[2][4][4];
#pragma unroll
        for (int mt = 0; mt < 4; mt++) ldsm4(ra[0][mt], aAddr + mt * (16 * LDW * 2));
#pragma unroll
        for (int pr = 0; pr < 4; pr++) ldsm4(rb[0][pr], bAddr + pr * (16 * LDW * 2));

#pragma unroll
        for (int kk = 0; kk < BK; kk += 16) {
            const int cur = (kk >> 4) & 1;
            const int nxt = cur ^ 1;
            if (kk + 16 < BK) {
#pragma unroll
                for (int mt = 0; mt < 4; mt++)
                    ldsm4(ra[nxt][mt], aAddr + (kk + 16) * 2 + mt * (16 * LDW * 2));
#pragma unroll
                for (int pr = 0; pr < 4; pr++)
                    ldsm4(rb[nxt][pr], bAddr + (kk + 16) * 2 + pr * (16 * LDW * 2));
            }
#pragma unroll
            for (int mt = 0; mt < 4; mt++)
#pragma unroll
                for (int nt = 0; nt < 8; nt++)
                    mma16816(acc[mt][nt],
                             ra[cur][mt][0], ra[cur][mt][1], ra[cur][mt][2], ra[cur][mt][3],
                             rb[cur][nt >> 1][(nt & 1) * 2], rb[cur][nt >> 1][(nt & 1) * 2 + 1]);
        }
    }

    // ---- epilogue: direct fp32 stores (N always a multiple of 128 here)
#pragma unroll
    for (int mt = 0; mt < 4; mt++) {
#pragma unroll
        for (int nt = 0; nt < 8; nt++) {
            const int row = m0 + wm * 64 + mt * 16 + (lane >> 2);
            const int col = n0 + wn * 64 + nt * 8 + (lane & 3) * 2;
            *(float2*)(C + (size_t)row * N + col) =
                make_float2(acc[mt][nt][0], acc[mt][nt][1]);
            *(float2*)(C + (size_t)(row + 8) * N + col) =
                make_float2(acc[mt][nt][2], acc[mt][nt][3]);
        }
    }
}

// ---------------- conv(4)+SiLU+L2norm AND gate-param transform ---------------
constexpr int CONV_BLOCKS = MTOK * 48 / 8;   // 24576
__global__ __launch_bounds__(256) void conv_ab(const float* __restrict__ wconv,
                                               const float* __restrict__ A_log,
                                               const float* __restrict__ dt_bias)
{
    if (blockIdx.x >= CONV_BLOCKS) {
        const int idx = (blockIdx.x - CONV_BLOCKS) * 256 + threadIdx.x;
        if (idx >= MTOK * HV) return;
        const int t = idx >> 4, h = idx & 15;
        const float a  = g_proj[(size_t)t * NP + 3072 + h];
        const float bb = g_proj[(size_t)t * NP + 3072 + 16 + h];
        const float x  = a + dt_bias[h];
        const float sp = (x > 20.f) ? x : log1pf(expf(x));
        g_eg[idx]   = expf(-expf(A_log[h]) * sp);
        g_beta[idx] = 1.f / (1.f + expf(-bb));
        return;
    }
    const int gi   = blockIdx.x * 8 + (threadIdx.x >> 5);
    const int t    = gi / 48;
    const int grp  = gi % 48;
    const int lane = threadIdx.x & 31;
    const int batch = t >> 11;
    const int s     = t & 2047;

    float y[2];
#pragma unroll
    for (int hh = 0; hh < 2; hh++) {
        const int c = grp * 64 + lane + hh * 32;
        float acc = 0.f;
#pragma unroll
        for (int i = 0; i < 4; i++) {
            const int ss = s - 3 + i;
            if (ss >= 0)
                acc = fmaf(g_proj[(size_t)(batch * S + ss) * NP + c], wconv[c * 4 + i], acc);
        }
        y[hh] = acc / (1.f + expf(-acc));
    }
    if (grp < 32) {
        float ssum = y[0] * y[0] + y[1] * y[1];
#pragma unroll
        for (int o = 16; o; o >>= 1) ssum += __shfl_xor_sync(0xffffffffu, ssum, o);
        float inv = rsqrtf(ssum + 1e-6f);
        if (grp < 16) inv *= 0.125f;
        y[0] *= inv; y[1] *= inv;
    }
    g_conv[(size_t)t * CCH + grp * 64 + lane]      = y[0];
    g_conv[(size_t)t * CCH + grp * 64 + lane + 32] = y[1];
}

// ---------------- sequential gated delta scan (R15: v-split 4x, 8 thr/col) ---
__global__ __launch_bounds__(128, 1) void scan_kernel()
{
    constexpr int CH = 32;
    constexpr int VC = 16;
    const int bh  = blockIdx.x >> 2;
    const int vc0 = (blockIdx.x & 3) * VC;
    const int b   = bh >> 4, h = bh & 15;
    const int tid = threadIdx.x;
    const int v   = tid >> 3;        // 0..15 (local v column)
    const int r   = tid & 7;         // 8 k-elements each

    __shared__ __align__(16) float sq[2][CH][64], sk[2][CH][64], sv[2][CH][VC];
    __shared__ float seg[2][CH], sbeta[2][CH];

    const float* convBase = g_conv + (size_t)(b * S) * CCH;

    auto issueChunk = [&](int c64) {
        const int buf = c64 & 1;
        const int c0 = c64 * CH;
#pragma unroll
        for (int i = 0; i < 4; i++) {
            const int chunk = tid + i * 128;           // 0..511
            const int st = chunk >> 4, d4 = chunk & 15;
            const size_t row = (size_t)(c0 + st) * CCH + h * 64 + d4 * 4;
            CP_ASYNC16(smem_u32(&sq[buf][st][d4 * 4]), convBase + row);
            CP_ASYNC16(smem_u32(&sk[buf][st][d4 * 4]), convBase + row + 1024);
        }
        {   // sv: 32 steps x 16 cols = 128 float4
            const int st = tid >> 2, d4 = tid & 3;
            CP_ASYNC16(smem_u32(&sv[buf][st][d4 * 4]),
                       convBase + (size_t)(c0 + st) * CCH + 2048 + h * 64 + vc0 + d4 * 4);
        }
        if (tid < CH) {
            const int token = b * S + c0 + tid;
            CP_ASYNC4(smem_u32(&seg[buf][tid]),   g_eg   + token * HV + h);
            CP_ASYNC4(smem_u32(&sbeta[buf][tid]), g_beta + token * HV + h);
        }
    };

    float hst[8];
#pragma unroll
    for (int j = 0; j < 8; j++) hst[j] = 0.f;

    issueChunk(0); CP_COMMIT();

    for (int c64 = 0; c64 < S / CH; c64++) {
        if (c64 + 1 < S / CH) issueChunk(c64 + 1);
        CP_COMMIT();
        CP_WAIT1();
        __syncthreads();
        const int buf = c64 & 1;
        const int c0 = c64 * CH;

        float4 ck0 = *(const float4*)&sk[buf][0][r * 8];
        float4 ck1 = *(const float4*)&sk[buf][0][r * 8 + 4];
        float ce    = seg[buf][0];
        float cbt   = sbeta[buf][0];
        float cnbte = -cbt * ce;
        float cbtv  = cbt * sv[buf][0][v];

#pragma unroll 4
        for (int st = 0; st < CH; st++) {
            const int sn = (st + 1 < CH) ? st + 1 : st;
            const float4 nk0 = *(const float4*)&sk[buf][sn][r * 8];
            const float4 nk1 = *(const float4*)&sk[buf][sn][r * 8 + 4];
            const float ne    = seg[buf][sn];
            const float nbt   = sbeta[buf][sn];
            const float nnbte = -nbt * ne;
            const float nbtv  = nbt * sv[buf][sn][v];

            const float4 q0 = *(const float4*)&sq[buf][st][r * 8];
            const float4 q1 = *(const float4*)&sq[buf][st][r * 8 + 4];

            float a = ck0.x * hst[0];
            float bb2 = ck0.y * hst[1];
            float c = ck0.z * hst[2];
            float d = ck0.w * hst[3];
            a = fmaf(ck1.x, hst[4], a);
            bb2 = fmaf(ck1.y, hst[5], bb2);
            c = fmaf(ck1.z, hst[6], c);
            d = fmaf(ck1.w, hst[7], d);
            float s1 = (a + bb2) + (c + d);
            s1 += __shfl_xor_sync(0xffffffffu, s1, 1);
            s1 += __shfl_xor_sync(0xffffffffu, s1, 2);
            s1 += __shfl_xor_sync(0xffffffffu, s1, 4);
            const float delta = fmaf(cnbte, s1, cbtv);

            const float kk[8] = {ck0.x, ck0.y, ck0.z, ck0.w, ck1.x, ck1.y, ck1.z, ck1.w};
            const float qq[8] = {q0.x, q0.y, q0.z, q0.w, q1.x, q1.y, q1.z, q1.w};

            float oA = 0.f, oB = 0.f;
#pragma unroll
            for (int j = 0; j < 4; j++) {
                hst[j] = fmaf(hst[j], ce, kk[j] * delta);
                oA = fmaf(qq[j], hst[j], oA);
            }
#pragma unroll
            for (int j = 4; j < 8; j++) {
                hst[j] = fmaf(hst[j], ce, kk[j] * delta);
                oB = fmaf(qq[j], hst[j], oB);
            }
            float oo = oA + oB;
            oo += __shfl_xor_sync(0xffffffffu, oo, 1);
            oo += __shfl_xor_sync(0xffffffffu, oo, 2);
            oo += __shfl_xor_sync(0xffffffffu, oo, 4);
            if (r == 0)
                g_oatt[((size_t)(b * S + c0 + st) * HV + h) * 64 + vc0 + v] = oo;

            ck0 = nk0; ck1 = nk1;
            ce = ne; cnbte = nnbte; cbtv = nbtv;
        }
        __syncthreads();
    }
}

// ---------------- gate*silu + RMSNorm, writes bf16 [hi|hi|lo] ----------------
__global__ __launch_bounds__(128) void gate_norm(const float* __restrict__ rms_w)
{
    const int gidx = blockIdx.x * 4 + (threadIdx.x >> 5);
    const int lane = threadIdx.x & 31;
    const int t = gidx >> 4, h = gidx & 15;
    const size_t base = (size_t)gidx * 64;

    float x[2];
#pragma unroll
    for (int hh = 0; hh < 2; hh++) {
        const int d = lane + hh * 32;
        const float o  = g_oatt[base + d];
        const float gt = g_proj[(size_t)t * NP + 3072 + 32 + h * 64 + d];
        x[hh] = o * (gt / (1.f + expf(-gt)));
    }
    float ms = x[0] * x[0] + x[1] * x[1];
#pragma unroll
    for (int o = 16; o; o >>= 1) ms += __shfl_xor_sync(0xffffffffu, ms, o);
    const float inv = rsqrtf(ms * (1.f / 64.f) + 1e-5f);
#pragma unroll
    for (int hh = 0; hh < 2; hh++) {
        const int d = lane + hh * 32;
        const float y = x[hh] * inv * rms_w[d];
        __nv_bfloat16 hi = __float2bfloat16(y);
        __nv_bfloat16 lo = __float2bfloat16(y - __bfloat162float(hi));
        const size_t o = (size_t)t * KT + h * 64 + d;
        g_on2[o]        = hi;
        g_on2[o + 1024] = hi;
        g_on2[o + 2048] = lo;
    }
}

// ---------------- launch ----------------------------------------------------
extern "C" void kernel_launch(void* const* d_in, const int* in_sizes, int n_in,
                              void* d_out, int out_size)
{
    const float* hidden  = (const float*)d_in[0];
    const float* w_qkv   = (const float*)d_in[1];
    const float* w_ab    = (const float*)d_in[2];
    const float* w_conv  = (const float*)d_in[3];
    const float* A_log   = (const float*)d_in[4];
    const float* dt_bias = (const float*)d_in[5];
    const float* rms_w   = (const float*)d_in[6];
    const float* w_o     = (const float*)d_in[7];
    float* out = (float*)d_out;

    float* p_proj;
    __nv_bfloat16 *p_hid2, *p_w2, *p_wo2, *p_on2;
    cudaGetSymbolAddress((void**)&p_proj, g_proj);
    cudaGetSymbolAddress((void**)&p_hid2, g_hid2);
    cudaGetSymbolAddress((void**)&p_w2,   g_w2);
    cudaGetSymbolAddress((void**)&p_wo2,  g_wo2);
    cudaGetSymbolAddress((void**)&p_on2,  g_on2);

    cudaFuncSetAttribute(gemm_hmma, cudaFuncAttributeMaxDynamicSharedMemorySize, GEMM_SMEM);

    // 1-3) bf16 hi/lo splits (3 launches so the proj GEMM is the 4th = profiled)
    split3<<<MTOK * 1024 / 256, 256>>>(hidden, p_hid2, MTOK, MTOK, 0);
    split3<<<3072 * 1024 / 256, 256>>>(w_qkv, p_w2, 3072, 3072, 1);
    split_rest<<<2304 * 1024 / 256, 256>>>(w_ab, w_o);

    // 4) merged input projection (tensor cores) -- profiled by ncu
    gemm_hmma<<<dim3(NP / 128, MTOK / 128), 128, GEMM_SMEM>>>(p_hid2, p_w2, p_proj, NP);

    // 5) conv + gate params
    conv_ab<<<CONV_BLOCKS + MTOK * HV / 256, 256>>>(w_conv, A_log, dt_bias);

    // 6) recurrent scan (R15 config: v-split 4x, 8 thr/col)
    scan_kernel<<<B * HV * 4, 128>>>();

    // 7) gating + norm ; 8) output projection
    gate_norm<<<MTOK * HV / 4, 128>>>(rms_w);
    gemm_hmma<<<dim3(1024 / 128, MTOK / 128), 128, GEMM_SMEM>>>(p_on2, p_wo2, out, 1024);
}